// round 2
// baseline (speedup 1.0000x reference)
#include <cuda_runtime.h>
#include <cuda_bf16.h>
#include <cstddef>

// Problem constants
#define D_DIM   1024
#define L_COMP  16384
#define L_FULL  32768
#define EPS_P   1e-4f

// Chunking
#define NCHUNK  256
#define CHUNK_S 64            // NCHUNK * CHUNK_S == L_COMP
#define TPB     256           // 256 threads * float4 = 1024 channels

// Scratch (no cudaMalloc allowed)
__device__ float g_A[NCHUNK];                   // per-chunk decay product
__device__ float g_B[NCHUNK * D_DIM];           // per-chunk zero-init scan tail
__device__ float g_Z[NCHUNK * D_DIM];           // per-chunk entry state
__device__ int   g_start[L_COMP + 1];           // output run starts per compressed row

// ---------------------------------------------------------------------------
// Kernel 0: boundary scan. cumsum(b) over L_FULL, record start position of
// each compressed row j (b[t]==1 -> start[excl_prefix(t)] = t).
// One block, 256 threads, 128 elements each.
// ---------------------------------------------------------------------------
__global__ __launch_bounds__(TPB) void boundary_kernel(const int* __restrict__ b) {
    __shared__ int warp_sums[8];
    const int tid  = threadIdx.x;
    const int lane = tid & 31;
    const int w    = tid >> 5;
    const int base = tid * 128;

    int s = 0;
    for (int k = 0; k < 128; k++) s += b[base + k];

    // warp inclusive scan of per-thread sums
    int incl = s;
    #pragma unroll
    for (int o = 1; o < 32; o <<= 1) {
        int v = __shfl_up_sync(0xFFFFFFFFu, incl, o);
        if (lane >= o) incl += v;
    }
    if (lane == 31) warp_sums[w] = incl;
    __syncthreads();
    if (tid == 0) {
        int acc = 0;
        #pragma unroll
        for (int i = 0; i < 8; i++) { acc += warp_sums[i]; warp_sums[i] = acc; }
    }
    __syncthreads();

    int run = incl - s + (w ? warp_sums[w - 1] : 0);  // exclusive prefix
    for (int k = 0; k < 128; k++) {
        int bv = b[base + k];
        if (bv) g_start[run] = base + k;
        run += bv;
    }
    if (tid == 0) g_start[L_COMP] = L_FULL;
}

// ---------------------------------------------------------------------------
// Kernel 1: per-chunk zero-init scan -> B[c][d], and decay product A[c].
// grid = NCHUNK, block = TPB, float4 per thread (1024 channels / block).
// ---------------------------------------------------------------------------
__global__ __launch_bounds__(TPB) void pass1_kernel(const float* __restrict__ x,
                                                    const float* __restrict__ p) {
    const int c   = blockIdx.x;
    const int tid = threadIdx.x;
    __shared__ float ps[CHUNK_S];
    __shared__ float qs[CHUNK_S];

    for (int i = tid; i < CHUNK_S; i += TPB) {
        float pv = p[c * CHUNK_S + i];
        pv = fminf(fmaxf(pv, EPS_P), 1.0f - EPS_P);
        ps[i] = pv;
        qs[i] = 1.0f - pv;
    }
    __syncthreads();

    const float4* x4 = (const float4*)x + (size_t)c * CHUNK_S * (D_DIM / 4) + tid;
    float4 z = make_float4(0.f, 0.f, 0.f, 0.f);
    float a = 1.0f;

    #pragma unroll 4
    for (int i = 0; i < CHUNK_S; i++) {
        float4 xv = x4[i * (D_DIM / 4)];
        float pv = ps[i], qv = qs[i];
        a *= qv;
        z.x = fmaf(qv, z.x, pv * xv.x);
        z.y = fmaf(qv, z.y, pv * xv.y);
        z.z = fmaf(qv, z.z, pv * xv.z);
        z.w = fmaf(qv, z.w, pv * xv.w);
    }

    ((float4*)g_B)[c * (D_DIM / 4) + tid] = z;
    if (tid == 0) g_A[c] = a;
}

// ---------------------------------------------------------------------------
// Kernel 2: sequential combine over chunks -> entry state Z[c][d].
// One block of TPB threads; loads of B are carry-independent (MLP hides L2).
// ---------------------------------------------------------------------------
__global__ __launch_bounds__(TPB) void pass2_kernel() {
    const int tid = threadIdx.x;
    __shared__ float As[NCHUNK];
    for (int i = tid; i < NCHUNK; i += TPB) As[i] = g_A[i];
    __syncthreads();

    float4 carry = make_float4(0.f, 0.f, 0.f, 0.f);
    const float4* B4 = (const float4*)g_B;
    float4* Z4 = (float4*)g_Z;

    #pragma unroll 4
    for (int c = 0; c < NCHUNK; c++) {
        Z4[c * (D_DIM / 4) + tid] = carry;
        float4 bv = B4[c * (D_DIM / 4) + tid];
        float a = As[c];
        carry.x = fmaf(a, carry.x, bv.x);
        carry.y = fmaf(a, carry.y, bv.y);
        carry.z = fmaf(a, carry.z, bv.z);
        carry.w = fmaf(a, carry.w, bv.w);
    }
}

// ---------------------------------------------------------------------------
// Kernel 3: replay each chunk with its carry; for each compressed row write
// the result to its run of full-sequence rows [start[j], start[j+1]).
// ---------------------------------------------------------------------------
__global__ __launch_bounds__(TPB) void pass3_kernel(const float* __restrict__ x,
                                                    const float* __restrict__ p,
                                                    float* __restrict__ out) {
    const int c   = blockIdx.x;
    const int tid = threadIdx.x;
    __shared__ float ps[CHUNK_S];
    __shared__ float qs[CHUNK_S];
    __shared__ int   ss[CHUNK_S + 1];

    for (int i = tid; i < CHUNK_S; i += TPB) {
        float pv = p[c * CHUNK_S + i];
        pv = fminf(fmaxf(pv, EPS_P), 1.0f - EPS_P);
        ps[i] = pv;
        qs[i] = 1.0f - pv;
    }
    for (int i = tid; i < CHUNK_S + 1; i += TPB)
        ss[i] = g_start[c * CHUNK_S + i];
    __syncthreads();

    const float4* x4 = (const float4*)x + (size_t)c * CHUNK_S * (D_DIM / 4) + tid;
    float4 z = ((const float4*)g_Z)[c * (D_DIM / 4) + tid];
    float4* o4 = (float4*)out;

    for (int i = 0; i < CHUNK_S; i++) {
        float4 xv = x4[i * (D_DIM / 4)];
        float pv = ps[i], qv = qs[i];
        z.x = fmaf(qv, z.x, pv * xv.x);
        z.y = fmaf(qv, z.y, pv * xv.y);
        z.z = fmaf(qv, z.z, pv * xv.z);
        z.w = fmaf(qv, z.w, pv * xv.w);

        int s = ss[i];
        int e = ss[i + 1];
        float4* dst = o4 + (size_t)s * (D_DIM / 4) + tid;
        for (int r = s; r < e; r++) {
            *dst = z;
            dst += (D_DIM / 4);
        }
    }
}

// ---------------------------------------------------------------------------
extern "C" void kernel_launch(void* const* d_in, const int* in_sizes, int n_in,
                              void* d_out, int out_size) {
    const float* x = (const float*)d_in[0];
    const float* p = (const float*)d_in[1];
    const int*   b = (const int*)d_in[2];
    float* out = (float*)d_out;

    boundary_kernel<<<1, TPB>>>(b);
    pass1_kernel<<<NCHUNK, TPB>>>(x, p);
    pass2_kernel<<<1, TPB>>>();
    pass3_kernel<<<NCHUNK, TPB>>>(x, p, out);
}

// round 3
// speedup vs baseline: 2.4859x; 2.4859x over previous
#include <cuda_runtime.h>
#include <cuda_bf16.h>
#include <cstddef>

// Problem constants
#define D_DIM   1024
#define L_COMP  16384
#define L_FULL  32768
#define EPS_P   1e-4f

// Chunking
#define NCHUNK  512
#define CHUNK_S 32            // NCHUNK * CHUNK_S == L_COMP
#define NGROUP  16
#define GROUP_SZ (NCHUNK / NGROUP)   // 32 chunks per group
#define TPB     256           // 256 threads * float4 = 1024 channels
#define D4      (D_DIM / 4)

// Scratch (no cudaMalloc allowed)
__device__ float g_A[NCHUNK];                   // per-chunk decay product
__device__ float g_B[NCHUNK * D_DIM];           // per-chunk zero-init scan tail
__device__ float g_Apref[NCHUNK];               // exclusive A-prefix within group
__device__ float g_Zloc[NCHUNK * D_DIM];        // exclusive within-group prefix state
__device__ float g_GA[NGROUP];                  // group decay product
__device__ float g_GB[NGROUP * D_DIM];          // group aggregate
__device__ float g_E[NGROUP * D_DIM];           // group entry state
__device__ int   g_start[L_COMP + 1];           // output run starts per compressed row

// ---------------------------------------------------------------------------
// Fused kernel A: blocks [0, NCHUNK) do pass1 (per-chunk aggregates);
// block NCHUNK does the boundary scan (independent work, overlapped).
// ---------------------------------------------------------------------------
__global__ __launch_bounds__(TPB) void pass1_kernel(const float* __restrict__ x,
                                                    const float* __restrict__ p,
                                                    const int*   __restrict__ b) {
    const int tid = threadIdx.x;

    if (blockIdx.x == NCHUNK) {
        // ---- boundary scan: 256 threads * 128 elements (int4 vectorized) ----
        __shared__ int warp_sums[8];
        const int lane = tid & 31;
        const int w    = tid >> 5;
        const int base = tid * 128;
        const int4* b4 = (const int4*)(b + base);

        int s = 0;
        #pragma unroll
        for (int k = 0; k < 32; k++) {
            int4 v = b4[k];
            s += v.x + v.y + v.z + v.w;
        }
        int incl = s;
        #pragma unroll
        for (int o = 1; o < 32; o <<= 1) {
            int v = __shfl_up_sync(0xFFFFFFFFu, incl, o);
            if (lane >= o) incl += v;
        }
        if (lane == 31) warp_sums[w] = incl;
        __syncthreads();
        if (tid == 0) {
            int acc = 0;
            #pragma unroll
            for (int i = 0; i < 8; i++) { acc += warp_sums[i]; warp_sums[i] = acc; }
        }
        __syncthreads();

        int run = incl - s + (w ? warp_sums[w - 1] : 0);  // exclusive prefix
        #pragma unroll 8
        for (int k = 0; k < 128; k++) {
            int bv = b[base + k];
            if (bv) g_start[run] = base + k;
            run += bv;
        }
        if (tid == 0) g_start[L_COMP] = L_FULL;
        return;
    }

    // ---- pass1: per-chunk zero-init scan -> B[c][d], decay product A[c] ----
    const int c = blockIdx.x;
    __shared__ float ps[CHUNK_S];
    __shared__ float qs[CHUNK_S];

    if (tid < CHUNK_S) {
        float pv = p[c * CHUNK_S + tid];
        pv = fminf(fmaxf(pv, EPS_P), 1.0f - EPS_P);
        ps[tid] = pv;
        qs[tid] = 1.0f - pv;
    }
    __syncthreads();

    const float4* x4 = (const float4*)x + (size_t)c * CHUNK_S * D4 + tid;
    float4 z = make_float4(0.f, 0.f, 0.f, 0.f);

    #pragma unroll
    for (int i0 = 0; i0 < CHUNK_S; i0 += 4) {
        float4 xv0 = x4[(i0 + 0) * D4];
        float4 xv1 = x4[(i0 + 1) * D4];
        float4 xv2 = x4[(i0 + 2) * D4];
        float4 xv3 = x4[(i0 + 3) * D4];
        float pv, qv;
        pv = ps[i0 + 0]; qv = qs[i0 + 0];
        z.x = fmaf(qv, z.x, pv * xv0.x); z.y = fmaf(qv, z.y, pv * xv0.y);
        z.z = fmaf(qv, z.z, pv * xv0.z); z.w = fmaf(qv, z.w, pv * xv0.w);
        pv = ps[i0 + 1]; qv = qs[i0 + 1];
        z.x = fmaf(qv, z.x, pv * xv1.x); z.y = fmaf(qv, z.y, pv * xv1.y);
        z.z = fmaf(qv, z.z, pv * xv1.z); z.w = fmaf(qv, z.w, pv * xv1.w);
        pv = ps[i0 + 2]; qv = qs[i0 + 2];
        z.x = fmaf(qv, z.x, pv * xv2.x); z.y = fmaf(qv, z.y, pv * xv2.y);
        z.z = fmaf(qv, z.z, pv * xv2.z); z.w = fmaf(qv, z.w, pv * xv2.w);
        pv = ps[i0 + 3]; qv = qs[i0 + 3];
        z.x = fmaf(qv, z.x, pv * xv3.x); z.y = fmaf(qv, z.y, pv * xv3.y);
        z.z = fmaf(qv, z.z, pv * xv3.z); z.w = fmaf(qv, z.w, pv * xv3.w);
    }

    ((float4*)g_B)[c * D4 + tid] = z;
    if (tid == 0) {
        float a = 1.0f;
        #pragma unroll
        for (int i = 0; i < CHUNK_S; i++) a *= qs[i];
        g_A[c] = a;
    }
}

// ---------------------------------------------------------------------------
// Kernel B: per-group sequential combine. Each of NGROUP blocks combines its
// GROUP_SZ chunks: stores exclusive within-group prefixes (Zloc, Apref) and
// the group aggregate (GA, GB).
// ---------------------------------------------------------------------------
__global__ __launch_bounds__(TPB) void pass2a_kernel() {
    const int g   = blockIdx.x;
    const int tid = threadIdx.x;
    __shared__ float As[GROUP_SZ];
    if (tid < GROUP_SZ) As[tid] = g_A[g * GROUP_SZ + tid];
    __syncthreads();

    float4 carry = make_float4(0.f, 0.f, 0.f, 0.f);
    float apref = 1.0f;
    const float4* B4 = (const float4*)g_B;
    float4* Z4 = (float4*)g_Zloc;

    #pragma unroll 4
    for (int j = 0; j < GROUP_SZ; j++) {
        const int c = g * GROUP_SZ + j;
        Z4[c * D4 + tid] = carry;
        if (tid == 0) g_Apref[c] = apref;
        float4 bv = B4[c * D4 + tid];
        float a = As[j];
        apref *= a;
        carry.x = fmaf(a, carry.x, bv.x);
        carry.y = fmaf(a, carry.y, bv.y);
        carry.z = fmaf(a, carry.z, bv.z);
        carry.w = fmaf(a, carry.w, bv.w);
    }

    ((float4*)g_GB)[g * D4 + tid] = carry;
    if (tid == 0) g_GA[g] = apref;
}

// ---------------------------------------------------------------------------
// Kernel C: sequential combine over groups -> group entry state E[g][d].
// ---------------------------------------------------------------------------
__global__ __launch_bounds__(TPB) void pass2b_kernel() {
    const int tid = threadIdx.x;
    __shared__ float As[NGROUP];
    if (tid < NGROUP) As[tid] = g_GA[tid];
    __syncthreads();

    float4 carry = make_float4(0.f, 0.f, 0.f, 0.f);
    const float4* GB4 = (const float4*)g_GB;
    float4* E4 = (float4*)g_E;

    #pragma unroll
    for (int g = 0; g < NGROUP; g++) {
        E4[g * D4 + tid] = carry;
        float4 bv = GB4[g * D4 + tid];
        float a = As[g];
        carry.x = fmaf(a, carry.x, bv.x);
        carry.y = fmaf(a, carry.y, bv.y);
        carry.z = fmaf(a, carry.z, bv.z);
        carry.w = fmaf(a, carry.w, bv.w);
    }
}

// ---------------------------------------------------------------------------
// Kernel D: replay each chunk with entry = Apref[c]*E[group] + Zloc[c];
// write each scanned row to its contiguous run [start[j], start[j+1]) of the
// full output. Loads batched 4-wide for MLP.
// ---------------------------------------------------------------------------
__global__ __launch_bounds__(TPB) void pass3_kernel(const float* __restrict__ x,
                                                    const float* __restrict__ p,
                                                    float* __restrict__ out) {
    const int c   = blockIdx.x;
    const int g   = c / GROUP_SZ;
    const int tid = threadIdx.x;
    __shared__ float ps[CHUNK_S];
    __shared__ float qs[CHUNK_S];
    __shared__ int   ss[CHUNK_S + 1];

    if (tid < CHUNK_S) {
        float pv = p[c * CHUNK_S + tid];
        pv = fminf(fmaxf(pv, EPS_P), 1.0f - EPS_P);
        ps[tid] = pv;
        qs[tid] = 1.0f - pv;
    }
    if (tid < CHUNK_S + 1) ss[tid] = g_start[c * CHUNK_S + tid];
    __syncthreads();

    // entry state for this chunk
    float4 zl = ((const float4*)g_Zloc)[c * D4 + tid];
    float4 ev = ((const float4*)g_E)[g * D4 + tid];
    float ap = g_Apref[c];
    float4 z;
    z.x = fmaf(ap, ev.x, zl.x);
    z.y = fmaf(ap, ev.y, zl.y);
    z.z = fmaf(ap, ev.z, zl.z);
    z.w = fmaf(ap, ev.w, zl.w);

    const float4* x4 = (const float4*)x + (size_t)c * CHUNK_S * D4 + tid;
    float4* o4 = (float4*)out;

    #pragma unroll
    for (int i0 = 0; i0 < CHUNK_S; i0 += 4) {
        // batched independent loads (MLP=4)
        float4 xv0 = x4[(i0 + 0) * D4];
        float4 xv1 = x4[(i0 + 1) * D4];
        float4 xv2 = x4[(i0 + 2) * D4];
        float4 xv3 = x4[(i0 + 3) * D4];

        float pv, qv;
        pv = ps[i0 + 0]; qv = qs[i0 + 0];
        z.x = fmaf(qv, z.x, pv * xv0.x); z.y = fmaf(qv, z.y, pv * xv0.y);
        z.z = fmaf(qv, z.z, pv * xv0.z); z.w = fmaf(qv, z.w, pv * xv0.w);
        float4 z0 = z;
        pv = ps[i0 + 1]; qv = qs[i0 + 1];
        z.x = fmaf(qv, z.x, pv * xv1.x); z.y = fmaf(qv, z.y, pv * xv1.y);
        z.z = fmaf(qv, z.z, pv * xv1.z); z.w = fmaf(qv, z.w, pv * xv1.w);
        float4 z1 = z;
        pv = ps[i0 + 2]; qv = qs[i0 + 2];
        z.x = fmaf(qv, z.x, pv * xv2.x); z.y = fmaf(qv, z.y, pv * xv2.y);
        z.z = fmaf(qv, z.z, pv * xv2.z); z.w = fmaf(qv, z.w, pv * xv2.w);
        float4 z2 = z;
        pv = ps[i0 + 3]; qv = qs[i0 + 3];
        z.x = fmaf(qv, z.x, pv * xv3.x); z.y = fmaf(qv, z.y, pv * xv3.y);
        z.z = fmaf(qv, z.z, pv * xv3.z); z.w = fmaf(qv, z.w, pv * xv3.w);
        float4 z3 = z;

        // store runs (no load dependencies here; stores stream out)
        int s0 = ss[i0 + 0], s1 = ss[i0 + 1], s2 = ss[i0 + 2],
            s3 = ss[i0 + 3], s4 = ss[i0 + 4];
        float4* dst;
        dst = o4 + (size_t)s0 * D4 + tid;
        for (int r = s0; r < s1; r++) { *dst = z0; dst += D4; }
        dst = o4 + (size_t)s1 * D4 + tid;
        for (int r = s1; r < s2; r++) { *dst = z1; dst += D4; }
        dst = o4 + (size_t)s2 * D4 + tid;
        for (int r = s2; r < s3; r++) { *dst = z2; dst += D4; }
        dst = o4 + (size_t)s3 * D4 + tid;
        for (int r = s3; r < s4; r++) { *dst = z3; dst += D4; }
    }
}

// ---------------------------------------------------------------------------
extern "C" void kernel_launch(void* const* d_in, const int* in_sizes, int n_in,
                              void* d_out, int out_size) {
    const float* x = (const float*)d_in[0];
    const float* p = (const float*)d_in[1];
    const int*   b = (const int*)d_in[2];
    float* out = (float*)d_out;

    pass1_kernel<<<NCHUNK + 1, TPB>>>(x, p, b);
    pass2a_kernel<<<NGROUP, TPB>>>();
    pass2b_kernel<<<1, TPB>>>();
    pass3_kernel<<<NCHUNK, TPB>>>(x, p, out);
}